// round 7
// baseline (speedup 1.0000x reference)
#include <cuda_runtime.h>
#include <cuda_fp16.h>
#include <cstdint>

// ===========================================================================
// FusionModel via mma.sync m16n8k16 fp16 (R4 trunk + occupancy fix).
//   H1pre = x @ W1,  x[b,(i*64+j)*64+k] = v1e[b,i]*v2e[b,j]*v3e[b,k]
//   M=256, N=256, K=262144.
// Grid: 2 mtile x 2 ntile x 74 chunks = 296 CTAs = 2 CTAs/SM (16 warps/SM)
//   so one CTA's HMMA stream covers the other's serial A-gen/barrier window.
// Per slab: B32 = W1 half-slab (64k x 128n fp32) via cp.async, double-buffered,
//   swizzled; inline fp32->fp16 pack at B-fragment load (R4-proven). A rank-1,
//   generated fp16 in smem from fp16 v3 tile x per-slab scalar (prefetched).
//   Split-K atomicAdd into g_acc; epilogue kernel finishes the MLP.
// ===========================================================================

namespace {
constexpr int BATCH = 256;
constexpr int DIN   = 63;
constexpr int H1    = 256;
constexpr int H2    = 128;
constexpr float EPSV  = 1e-5f;
constexpr float SLOPE = 0.1f;

constexpr int NSLABS  = 4096;
constexpr int NCHUNKS = 74;
constexpr int NT      = 256;

// SMEM map (bytes)
constexpr int SMB    = 32768;              // one B32 half-slab: 64k x 128n fp32
constexpr int SM_B32 = 0;                  // 2 x 32 KB
constexpr int SM_A16 = 2 * SMB;            // 65536: 128 rows x 144 B (fp16 A)
constexpr int SM_V3H = SM_A16 + 18432;     // 83968: 128 rows x 144 B (fp16 v3)
constexpr int SM_TOTAL = SM_V3H + 18432;   // 102400 -> 2 CTAs/SM
}

__device__ float g_acc[BATCH * H1];

__global__ void k_zero() {
    int i = blockIdx.x * blockDim.x + threadIdx.x;
    if (i < BATCH * H1) g_acc[i] = 0.0f;
}

// ---- helpers --------------------------------------------------------------
__device__ __forceinline__ uint32_t smem_u32(const void* p) {
    uint32_t a;
    asm("{ .reg .u64 t; cvta.to.shared.u64 t, %1; cvt.u32.u64 %0, t; }"
        : "=r"(a) : "l"(p));
    return a;
}
__device__ __forceinline__ uint32_t pkh2(float lo, float hi) {
    uint32_t d;
    asm("cvt.rn.f16x2.f32 %0, %1, %2;" : "=r"(d) : "f"(hi), "f"(lo));
    return d;
}
__device__ __forceinline__ uint32_t hmul2(uint32_t a, uint32_t b) {
    uint32_t d;
    asm("mul.rn.f16x2 %0, %1, %2;" : "=r"(d) : "r"(a), "r"(b));
    return d;
}
__device__ __forceinline__ void mma_f16(float* c, const uint32_t* a,
                                        const uint32_t* b) {
    asm volatile(
        "mma.sync.aligned.m16n8k16.row.col.f32.f16.f16.f32 "
        "{%0,%1,%2,%3}, {%4,%5,%6,%7}, {%8,%9}, {%0,%1,%2,%3};"
        : "+f"(c[0]), "+f"(c[1]), "+f"(c[2]), "+f"(c[3])
        : "r"(a[0]), "r"(a[1]), "r"(a[2]), "r"(a[3]), "r"(b[0]), "r"(b[1]));
}
__device__ __forceinline__ void cp16(uint32_t dst, const void* src) {
    asm volatile("cp.async.cg.shared.global [%0], [%1], 16;"
                 :: "r"(dst), "l"(src));
}
#define CP_COMMIT() asm volatile("cp.async.commit_group;" ::: "memory")
#define CP_WAIT1()  asm volatile("cp.async.wait_group 1;" ::: "memory")
#define CP_WAIT0()  asm volatile("cp.async.wait_group 0;" ::: "memory")

__device__ __forceinline__ int clsk(int k) { return ((k >> 1) & 3) << 1; }
// float index of B[k][n] in a 64x128 swizzled slab (k:0..63, n:0..127)
__device__ __forceinline__ int bidx(int k, int n) {
    return k * 128 + (((n >> 2) ^ clsk(k)) << 2) + (n & 3);
}

// ---------------------------------------------------------------------------
__global__ __launch_bounds__(NT, 2)
void k_gemm_mma(const float* __restrict__ v1, const float* __restrict__ v2,
                const float* __restrict__ v3, const float* __restrict__ W1) {
    extern __shared__ char smem[];
    const uint32_t b32_u32 = smem_u32(smem) + SM_B32;

    const int tid = threadIdx.x;
    const int wid = tid >> 5, l = tid & 31;
    const int lq = l >> 2, lr = l & 3;
    const int wm = wid >> 2, wn = wid & 3;
    const int mr = wm * 64, ncol = wn * 32;

    const int mtile = blockIdx.x & 1;
    const int ntile = blockIdx.x >> 1;
    const int chunk = blockIdx.y;
    const int s_lo = (chunk * NSLABS) / NCHUNKS;
    const int s_hi = ((chunk + 1) * NSLABS) / NCHUNKS;

    // A-gen ownership: row tb, k-half hh
    const int tb = tid >> 1, hh = tid & 1;
    const int bg = mtile * 128 + tb;

    // ---- v3 fp16 tile, once: [128 rows][144 B] ----
    for (int idx = tid; idx < 128 * 64; idx += NT) {
        int r = idx >> 6, c = idx & 63;
        float v = (c < DIN) ? v3[(mtile * 128 + r) * DIN + c] : 1.0f;
        *(__half*)(smem + SM_V3H + r * 144 + c * 2) = __float2half_rn(v);
    }

    // cp ownership: k-row ck, n-window cq*32
    const int ck = tid & 63;
    const int cq = tid >> 6;           // 0..3

    auto issue = [&](int s, int p) {
        const float* base = W1 + (size_t)s * 64 * H1 + (size_t)ck * H1 +
                            ntile * 128 + cq * 32;
        uint32_t bb = b32_u32 + (uint32_t)p * SMB;
#pragma unroll
        for (int it = 0; it < 8; ++it) {
            int nc = cq * 8 + it;
            uint32_t dst = bb + (uint32_t)((ck * 32 + (nc ^ clsk(ck))) * 16);
            cp16(dst, base + it * 4);
        }
        CP_COMMIT();
    };

    issue(s_lo, 0);
    if (s_lo + 1 < s_hi) issue(s_lo + 1, 1);

    // prefetch first slab's scalars
    float ai_c, cj_c;
    {
        int i = s_lo >> 6, j = s_lo & 63;
        ai_c = (i < DIN) ? __ldg(v1 + bg * DIN + i) : 1.0f;
        cj_c = (j < DIN) ? __ldg(v2 + bg * DIN + j) : 1.0f;
    }

    float acc[4][4][4];
#pragma unroll
    for (int mt = 0; mt < 4; ++mt)
#pragma unroll
        for (int nt = 0; nt < 4; ++nt)
#pragma unroll
            for (int q = 0; q < 4; ++q) acc[mt][nt][q] = 0.0f;

    __syncthreads();   // v3h ready

    for (int s = s_lo; s < s_hi; ++s) {
        const int sl = s - s_lo;
        const int p = sl & 1;
        const float* Bp = (const float*)(smem + SM_B32 + p * SMB);

        // ---- A gen: fp16 A[m][k] = v3h * f16(sv) (after sync2(s-1)) ----
        {
            float sv = ai_c * cj_c;
            uint32_t hs = pkh2(sv, sv);
            const uint4* vrow = (const uint4*)(smem + SM_V3H + tb * 144 + hh * 64);
            uint32_t* ad = (uint32_t*)(smem + SM_A16) + tb * 36 + hh * 16;
#pragma unroll
            for (int g = 0; g < 4; ++g) {
                uint4 r = vrow[g];
                r.x = hmul2(r.x, hs);
                r.y = hmul2(r.y, hs);
                r.z = hmul2(r.z, hs);
                r.w = hmul2(r.w, hs);
                *(uint4*)(ad + g * 4) = r;
            }
        }
        // prefetch next slab's scalars (latency hidden under this slab)
        float ai_n = 1.0f, cj_n = 1.0f;
        if (s + 1 < s_hi) {
            int i = (s + 1) >> 6, j = (s + 1) & 63;
            ai_n = (i < DIN) ? __ldg(v1 + bg * DIN + i) : 1.0f;
            cj_n = (j < DIN) ? __ldg(v2 + bg * DIN + j) : 1.0f;
        }

        if (s + 1 < s_hi) { CP_WAIT1(); } else { CP_WAIT0(); }
        __syncthreads();   // A16 + B32[p] visible

        // ---- mma over 4 k16 steps ----
#pragma unroll
        for (int kk = 0; kk < 4; ++kk) {
            const int kw = kk * 8 + lr;
            const int k0 = kk * 16 + lr * 2;
            uint32_t a[4][4];
#pragma unroll
            for (int mt = 0; mt < 4; ++mt) {
                const uint32_t* ar = (const uint32_t*)(smem + SM_A16) +
                                     (mr + mt * 16 + lq) * 36;
                a[mt][0] = ar[kw];
                a[mt][1] = ar[8 * 36 + kw];
                a[mt][2] = ar[kw + 4];
                a[mt][3] = ar[8 * 36 + kw + 4];
            }
            uint32_t bfr[4][2];
#pragma unroll
            for (int nt = 0; nt < 4; ++nt) {
                const int n = ncol + nt * 8 + lq;
                bfr[nt][0] = pkh2(Bp[bidx(k0, n)],     Bp[bidx(k0 + 1, n)]);
                bfr[nt][1] = pkh2(Bp[bidx(k0 + 8, n)], Bp[bidx(k0 + 9, n)]);
            }
#pragma unroll
            for (int mt = 0; mt < 4; ++mt)
#pragma unroll
                for (int nt = 0; nt < 4; ++nt)
                    mma_f16(acc[mt][nt], a[mt], bfr[nt]);
        }
        __syncthreads();   // B32[p] + A16 consumed

        if (s + 2 < s_hi) issue(s + 2, p);
        ai_c = ai_n; cj_c = cj_n;
    }

    // ---- split-K reduction ----
#pragma unroll
    for (int mt = 0; mt < 4; ++mt) {
        const int row = mtile * 128 + mr + mt * 16 + lq;
#pragma unroll
        for (int nt = 0; nt < 4; ++nt) {
            const int col = ntile * 128 + ncol + nt * 8 + lr * 2;
            atomicAdd(g_acc + row * H1 + col,           acc[mt][nt][0]);
            atomicAdd(g_acc + row * H1 + col + 1,       acc[mt][nt][1]);
            atomicAdd(g_acc + (row + 8) * H1 + col,     acc[mt][nt][2]);
            atomicAdd(g_acc + (row + 8) * H1 + col + 1, acc[mt][nt][3]);
        }
    }
}

// ---------------------------------------------------------------------------
__global__ __launch_bounds__(H2)
void k_epi(const float* __restrict__ b1,  const float* __restrict__ g1,
           const float* __restrict__ be1, const float* __restrict__ rm1,
           const float* __restrict__ rv1, const float* __restrict__ W2,
           const float* __restrict__ b2,  const float* __restrict__ g2,
           const float* __restrict__ be2, const float* __restrict__ rm2,
           const float* __restrict__ rv2, const float* __restrict__ Wc,
           const float* __restrict__ bc,  float* __restrict__ out) {
    __shared__ float h1s[H1];
    __shared__ float red[H2];
    const int b = blockIdx.x;
    const int t = threadIdx.x;

    for (int h = t; h < H1; h += H2) {
        float x = g_acc[b * H1 + h] + b1[h];
        x = (x >= 0.0f) ? x : SLOPE * x;
        x = (x - rm1[h]) * rsqrtf(rv1[h] + EPSV) * g1[h] + be1[h];
        h1s[h] = x;
    }
    __syncthreads();

    float a = 0.0f;
#pragma unroll 8
    for (int i = 0; i < H1; i++) a += h1s[i] * W2[i * H2 + t];
    a += b2[t];
    a = (a >= 0.0f) ? a : SLOPE * a;
    a = (a - rm2[t]) * rsqrtf(rv2[t] + EPSV) * g2[t] + be2[t];
    red[t] = a * Wc[t];
    __syncthreads();

    for (int sft = H2 / 2; sft > 0; sft >>= 1) {
        if (t < sft) red[t] += red[t + sft];
        __syncthreads();
    }
    if (t == 0) out[b] = red[0] + bc[0];
}

// ---------------------------------------------------------------------------
extern "C" void kernel_launch(void* const* d_in, const int* in_sizes, int n_in,
                              void* d_out, int out_size) {
    const float* vec1  = (const float*)d_in[0];
    const float* vec2  = (const float*)d_in[1];
    const float* vec3  = (const float*)d_in[2];
    const float* W1    = (const float*)d_in[3];
    const float* b1    = (const float*)d_in[4];
    const float* g1    = (const float*)d_in[5];
    const float* beta1 = (const float*)d_in[6];
    const float* rm1   = (const float*)d_in[7];
    const float* rv1   = (const float*)d_in[8];
    const float* W2    = (const float*)d_in[9];
    const float* b2    = (const float*)d_in[10];
    const float* g2    = (const float*)d_in[11];
    const float* beta2 = (const float*)d_in[12];
    const float* rm2   = (const float*)d_in[13];
    const float* rv2   = (const float*)d_in[14];
    const float* Wc    = (const float*)d_in[15];
    const float* bc    = (const float*)d_in[16];
    float* out = (float*)d_out;

    cudaFuncSetAttribute(k_gemm_mma,
                         cudaFuncAttributeMaxDynamicSharedMemorySize, SM_TOTAL);

    k_zero<<<(BATCH * H1 + 1023) / 1024, 1024>>>();

    dim3 grid(4, NCHUNKS);   // (mtile,ntile) x chunks = 296 CTAs, 2/SM
    k_gemm_mma<<<grid, NT, SM_TOTAL>>>(vec1, vec2, vec3, W1);

    k_epi<<<BATCH, H2>>>(b1, g1, beta1, rm1, rv1, W2, b2, g2, beta2,
                         rm2, rv2, Wc, bc, out);
}

// round 8
// speedup vs baseline: 1.0546x; 1.0546x over previous
#include <cuda_runtime.h>
#include <cstdint>

// ===========================================================================
// FusionModel via mma.sync m16n8k16 fp16 — R4 trunk + deterministic partials.
//   H1pre = x @ W1,  x[b,(i*64+j)*64+k] = v1e[b,i]*v2e[b,j]*v3e[b,k]
//   M=256, N=256, K=262144. Grid: 2 mtiles x 74 K-chunks = 148 CTAs (1 wave).
// Per slab (R4-proven): B32 = W1 slab via cp.async double-buffered swizzled;
//   A rank-1 fp16 in smem from register v3 + prefetched per-slab scalar;
//   inline fp32->fp16 pack at B-fragment load; 128 HMMA/warp/slab.
// NEW: no atomics/k_zero — each CTA writes coalesced partials to g_part;
//   k_epi reduces 74 chunks then finishes the MLP. Last-slab wait fixed.
// ===========================================================================

namespace {
constexpr int BATCH = 256;
constexpr int DIN   = 63;
constexpr int H1    = 256;
constexpr int H2    = 128;
constexpr float EPSV  = 1e-5f;
constexpr float SLOPE = 0.1f;

constexpr int NSLABS  = 4096;
constexpr int NCHUNKS = 74;
constexpr int NT      = 256;

constexpr int SMB_BYTES = 65536;        // B slab: 64k x 256n fp32 (swizzled)
constexpr int SMA_BYTES = 128 * 144;    // A slab: 128 rows x (64 half + pad)
constexpr int SM_B   = 0;               // 2 x 64 KB
constexpr int SM_A   = 2 * SMB_BYTES;   // 131072, 2 x 18432
constexpr int SM_TOTAL = SM_A + 2 * SMA_BYTES;   // 167936 B
constexpr int A_WSTRIDE = 36;           // words per A row (144 B)
}

// per-(chunk,mtile) partial tiles: [148][32768] floats = 19.4 MB
__device__ float g_part[2 * NCHUNKS * 32768];

// ---- helpers --------------------------------------------------------------
__device__ __forceinline__ uint32_t smem_u32(const void* p) {
    uint32_t a;
    asm("{ .reg .u64 t; cvta.to.shared.u64 t, %1; cvt.u32.u64 %0, t; }"
        : "=r"(a) : "l"(p));
    return a;
}
__device__ __forceinline__ uint32_t pkh2(float lo, float hi) {
    uint32_t d;
    asm("cvt.rn.f16x2.f32 %0, %1, %2;" : "=r"(d) : "f"(hi), "f"(lo));
    return d;
}
__device__ __forceinline__ void mma_f16(float* c, const uint32_t* a,
                                        const uint32_t* b) {
    asm volatile(
        "mma.sync.aligned.m16n8k16.row.col.f32.f16.f16.f32 "
        "{%0,%1,%2,%3}, {%4,%5,%6,%7}, {%8,%9}, {%0,%1,%2,%3};"
        : "+f"(c[0]), "+f"(c[1]), "+f"(c[2]), "+f"(c[3])
        : "r"(a[0]), "r"(a[1]), "r"(a[2]), "r"(a[3]), "r"(b[0]), "r"(b[1]));
}
__device__ __forceinline__ void cp16(uint32_t dst, const void* src) {
    asm volatile("cp.async.cg.shared.global [%0], [%1], 16;"
                 :: "r"(dst), "l"(src));
}
#define CP_COMMIT() asm volatile("cp.async.commit_group;" ::: "memory")
#define CP_WAIT1()  asm volatile("cp.async.wait_group 1;" ::: "memory")
#define CP_WAIT0()  asm volatile("cp.async.wait_group 0;" ::: "memory")

// ---------------------------------------------------------------------------
__global__ __launch_bounds__(NT, 1)
void k_gemm_mma(const float* __restrict__ v1, const float* __restrict__ v2,
                const float* __restrict__ v3, const float* __restrict__ W1) {
    extern __shared__ char smem[];
    float*    Bsm = (float*)(smem + SM_B);
    uint32_t* Asm = (uint32_t*)(smem + SM_A);   // [2][128 rows][36 words]
    const uint32_t b_u32 = smem_u32(Bsm);

    const int tid = threadIdx.x;
    const int wid = tid >> 5, l = tid & 31;
    const int lq = l >> 2, lr = l & 3;
    const int wm = wid >> 2, wn = wid & 3;
    const int mr = wm * 64, ncol = wn * 64;

    const int mtile = blockIdx.x;
    const int chunk = blockIdx.y;
    const int s_lo = (chunk * NSLABS) / NCHUNKS;
    const int s_hi = ((chunk + 1) * NSLABS) / NCHUNKS;

    // A-gen ownership: row tb, k-half hh; v3 register-resident
    const int tb = tid >> 1, hh = tid & 1;
    const int bg = mtile * 128 + tb;
    float v3r[32];
#pragma unroll
    for (int q = 0; q < 32; ++q) {
        int kk = hh * 32 + q;
        v3r[q] = (kk < DIN) ? v3[bg * DIN + kk] : 1.0f;
    }

    // cp ownership: row ck, n-window cq*64
    const int ck = tid & 63;
    const int cq = tid >> 6;

    auto issue = [&](int s, int p) {
        const float* base = W1 + (size_t)s * 64 * H1 + (size_t)ck * H1 + cq * 64;
        uint32_t bb = b_u32 + (uint32_t)p * SMB_BYTES;
#pragma unroll
        for (int it = 0; it < 16; ++it) {
            int nc = cq * 16 + it;
            uint32_t dst = bb + (uint32_t)((ck * 64 + (nc ^ (((ck >> 1) & 3) << 1))) * 16);
            cp16(dst, base + it * 4);
        }
        CP_COMMIT();
    };

    issue(s_lo, 0);
    if (s_lo + 1 < s_hi) issue(s_lo + 1, 1);

    // prefetch first slab's scalars
    float ai_c, cj_c;
    {
        int i = s_lo >> 6, j = s_lo & 63;
        ai_c = (i < DIN) ? __ldg(v1 + bg * DIN + i) : 1.0f;
        cj_c = (j < DIN) ? __ldg(v2 + bg * DIN + j) : 1.0f;
    }

    float acc[4][8][4];
#pragma unroll
    for (int mt = 0; mt < 4; ++mt)
#pragma unroll
        for (int nt = 0; nt < 8; ++nt)
#pragma unroll
            for (int q = 0; q < 4; ++q) acc[mt][nt][q] = 0.0f;

    // ---- hoisted fragment address bases (swizzle class 2*lr is per-lane
    //      constant across the whole slab: clsk(kk*16+lr*2 {+1,+8,+9}) = 2*lr)
    int bof[8];
#pragma unroll
    for (int nt = 0; nt < 8; ++nt) {
        int n = ncol + nt * 8 + lq;
        bof[nt] = (((n >> 2) ^ (lr << 1)) << 2) + (n & 3) + lr * 512;
    }
    int aof[4];
#pragma unroll
    for (int mt = 0; mt < 4; ++mt)
        aof[mt] = (mr + mt * 16 + lq) * A_WSTRIDE + lr;

    for (int s = s_lo; s < s_hi; ++s) {
        const int sl = s - s_lo;
        const int p = sl & 1;
        const float*    Bp = Bsm + p * (SMB_BYTES / 4);
        const uint32_t* Ap = Asm + p * (SMA_BYTES / 4);

        // ---- A gen: fp16 A[row][k] = cvt(sv * v3[b,k]) ----
        {
            float sv = ai_c * cj_c;
            uint32_t* dst = (uint32_t*)(smem + SM_A + p * SMA_BYTES) +
                            tb * A_WSTRIDE + hh * 16;
#pragma unroll
            for (int g = 0; g < 4; ++g) {
                uint4 v;
                v.x = pkh2(sv * v3r[g * 8 + 0], sv * v3r[g * 8 + 1]);
                v.y = pkh2(sv * v3r[g * 8 + 2], sv * v3r[g * 8 + 3]);
                v.z = pkh2(sv * v3r[g * 8 + 4], sv * v3r[g * 8 + 5]);
                v.w = pkh2(sv * v3r[g * 8 + 6], sv * v3r[g * 8 + 7]);
                *(uint4*)(dst + g * 4) = v;
            }
        }
        // prefetch next slab's scalars (latency hidden under wait+mma)
        float ai_n = 1.0f, cj_n = 1.0f;
        if (s + 1 < s_hi) {
            int i = (s + 1) >> 6, j = (s + 1) & 63;
            ai_n = (i < DIN) ? __ldg(v1 + bg * DIN + i) : 1.0f;
            cj_n = (j < DIN) ? __ldg(v2 + bg * DIN + j) : 1.0f;
        }

        if (s + 1 < s_hi) { CP_WAIT1(); } else { CP_WAIT0(); }
        __syncthreads();

#pragma unroll
        for (int kk = 0; kk < 4; ++kk) {
            const int ak = kk * 8;
            // A fragments (conflict-free LDS.32 half2; hoisted bases)
            uint32_t a[4][4];
#pragma unroll
            for (int mt = 0; mt < 4; ++mt) {
                const uint32_t* ar = Ap + aof[mt];
                a[mt][0] = ar[ak];
                a[mt][1] = ar[8 * A_WSTRIDE + ak];
                a[mt][2] = ar[ak + 4];
                a[mt][3] = ar[8 * A_WSTRIDE + ak + 4];
            }
            // B fragments (fp32 loads via hoisted bases, RNE pack to fp16)
            const int bk = kk * 4096;
            uint32_t bfr[8][2];
#pragma unroll
            for (int nt = 0; nt < 8; ++nt) {
                const float* bp = Bp + bof[nt] + bk;
                bfr[nt][0] = pkh2(bp[0],    bp[256]);
                bfr[nt][1] = pkh2(bp[2048], bp[2304]);
            }
#pragma unroll
            for (int mt = 0; mt < 4; ++mt)
#pragma unroll
                for (int nt = 0; nt < 8; ++nt)
                    mma_f16(acc[mt][nt], a[mt], bfr[nt]);
        }
        __syncthreads();

        if (s + 2 < s_hi) issue(s + 2, p);
        ai_c = ai_n; cj_c = cj_n;
    }

    // ---- coalesced partial store: g_part[cta][wid][mt*8+nt][l] (float4) ----
    float* part = g_part + ((size_t)(chunk * 2 + mtile)) * 32768 + wid * 4096;
#pragma unroll
    for (int mt = 0; mt < 4; ++mt)
#pragma unroll
        for (int nt = 0; nt < 8; ++nt)
            *(float4*)(part + (mt * 8 + nt) * 128 + l * 4) =
                make_float4(acc[mt][nt][0], acc[mt][nt][1],
                            acc[mt][nt][2], acc[mt][nt][3]);
}

// ---------------------------------------------------------------------------
__global__ __launch_bounds__(H1)
void k_epi(const float* __restrict__ b1,  const float* __restrict__ g1,
           const float* __restrict__ be1, const float* __restrict__ rm1,
           const float* __restrict__ rv1, const float* __restrict__ W2,
           const float* __restrict__ b2,  const float* __restrict__ g2,
           const float* __restrict__ be2, const float* __restrict__ rm2,
           const float* __restrict__ rv2, const float* __restrict__ Wc,
           const float* __restrict__ bc,  float* __restrict__ out) {
    __shared__ float h1s[H1];
    __shared__ float red[H2];
    const int b = blockIdx.x;
    const int t = threadIdx.x;      // h index, 256 threads

    // locate (b, h=t) inside the partial layout
    const int mtile = b >> 7, rr = b & 127;
    const int wm = rr >> 6, mt = (rr >> 4) & 3, ph = (rr >> 3) & 1, plq = rr & 7;
    const int wn = t >> 6, nt = (t >> 3) & 7, plr = (t & 7) >> 1, cpar = t & 1;
    const int wid = wm * 4 + wn, q = ph * 2 + cpar;
    const float* src = g_part + (size_t)mtile * 32768 + wid * 4096 +
                       (mt * 8 + nt) * 128 + (plq * 4 + plr) * 4 + q;

    float x = 0.0f;
#pragma unroll 2
    for (int c = 0; c < NCHUNKS; ++c) x += src[(size_t)c * 65536];

    x += b1[t];
    x = (x >= 0.0f) ? x : SLOPE * x;
    x = (x - rm1[t]) * rsqrtf(rv1[t] + EPSV) * g1[t] + be1[t];
    h1s[t] = x;
    __syncthreads();

    if (t < H2) {
        float a = 0.0f;
#pragma unroll 8
        for (int i = 0; i < H1; i++) a += h1s[i] * W2[i * H2 + t];
        a += b2[t];
        a = (a >= 0.0f) ? a : SLOPE * a;
        a = (a - rm2[t]) * rsqrtf(rv2[t] + EPSV) * g2[t] + be2[t];
        red[t] = a * Wc[t];
    }
    for (int sft = H2 / 2; sft > 0; sft >>= 1) {
        __syncthreads();
        if (t < sft) red[t] += red[t + sft];
    }
    __syncthreads();
    if (t == 0) out[b] = red[0] + bc[0];
}

// ---------------------------------------------------------------------------
extern "C" void kernel_launch(void* const* d_in, const int* in_sizes, int n_in,
                              void* d_out, int out_size) {
    const float* vec1  = (const float*)d_in[0];
    const float* vec2  = (const float*)d_in[1];
    const float* vec3  = (const float*)d_in[2];
    const float* W1    = (const float*)d_in[3];
    const float* b1    = (const float*)d_in[4];
    const float* g1    = (const float*)d_in[5];
    const float* beta1 = (const float*)d_in[6];
    const float* rm1   = (const float*)d_in[7];
    const float* rv1   = (const float*)d_in[8];
    const float* W2    = (const float*)d_in[9];
    const float* b2    = (const float*)d_in[10];
    const float* g2    = (const float*)d_in[11];
    const float* beta2 = (const float*)d_in[12];
    const float* rm2   = (const float*)d_in[13];
    const float* rv2   = (const float*)d_in[14];
    const float* Wc    = (const float*)d_in[15];
    const float* bc    = (const float*)d_in[16];
    float* out = (float*)d_out;

    cudaFuncSetAttribute(k_gemm_mma,
                         cudaFuncAttributeMaxDynamicSharedMemorySize, SM_TOTAL);

    dim3 grid(2, NCHUNKS);   // 148 CTAs = 1 wave
    k_gemm_mma<<<grid, NT, SM_TOTAL>>>(vec1, vec2, vec3, W1);

    k_epi<<<BATCH, H1>>>(b1, g1, beta1, rm1, rv1, W2, b2, g2, beta2,
                         rm2, rv2, Wc, bc, out);
}